// round 2
// baseline (speedup 1.0000x reference)
#include <cuda_runtime.h>
#include <math_constants.h>

// Kernel 1: one warp per row computes argmax over 512 fp32 values.
// Writes the argmax index as a *float32* (harness output dtype).
__global__ void ctc_argmax_kernel(const float* __restrict__ em,
                                  float* __restrict__ out_index,
                                  int T) {
    const int warps_per_block = blockDim.x >> 5;
    const int row = blockIdx.x * warps_per_block + (threadIdx.x >> 5);
    if (row >= T) return;
    const int lane = threadIdx.x & 31;

    const float4* __restrict__ p =
        reinterpret_cast<const float4*>(em + (size_t)row * 512);

    float best = -CUDART_INF_F;
    int bidx = 0x7fffffff;

    #pragma unroll
    for (int j = 0; j < 4; j++) {
        const int v4 = lane + 32 * j;         // float4 index within row
        const float4 v = __ldg(&p[v4]);
        const int base = v4 * 4;
        if (v.x > best || (v.x == best && base + 0 < bidx)) { best = v.x; bidx = base + 0; }
        if (v.y > best || (v.y == best && base + 1 < bidx)) { best = v.y; bidx = base + 1; }
        if (v.z > best || (v.z == best && base + 2 < bidx)) { best = v.z; bidx = base + 2; }
        if (v.w > best || (v.w == best && base + 3 < bidx)) { best = v.w; bidx = base + 3; }
    }

    // warp argmax reduction, first-occurrence tie-break
    #pragma unroll
    for (int off = 16; off > 0; off >>= 1) {
        float ov = __shfl_down_sync(0xffffffffu, best, off);
        int   oi = __shfl_down_sync(0xffffffffu, bidx, off);
        if (ov > best || (ov == best && oi < bidx)) { best = ov; bidx = oi; }
    }

    if (lane == 0) out_index[row] = (float)bidx;
}

// Kernel 2: compute keep mask from the (float-encoded) index array.
//   char:  index==0 -> -1 ; index>1 -> index-1 ; index==1 -> 0
//   keep[t] = (char[t] != char[t-1]) && (char[t] != -1); char[-1] = -2
__device__ __forceinline__ int ctc_char(int i) {
    return (i == 0) ? -1 : ((i > 1) ? (i - 1) : 0);
}

__global__ void ctc_keep_kernel(const float* __restrict__ index,
                                float* __restrict__ out_keep,
                                int T) {
    const int t = blockIdx.x * blockDim.x + threadIdx.x;
    if (t >= T) return;
    const int c = ctc_char((int)index[t]);
    int pc = -2;
    if (t > 0) pc = ctc_char((int)index[t - 1]);
    out_keep[t] = (c != pc && c != -1) ? 1.0f : 0.0f;
}

extern "C" void kernel_launch(void* const* d_in, const int* in_sizes, int n_in,
                              void* d_out, int out_size) {
    const float* emission = (const float*)d_in[0];
    const int V = 512;
    const int T = in_sizes[0] / V;   // 65536

    float* out = (float*)d_out;      // [0:T] index (as float), [T:2T] keep (0/1)
    float* out_index = out;
    float* out_keep  = out + T;

    const int threads = 256;                     // 8 warps = 8 rows per block
    const int rows_per_block = threads / 32;
    const int blocks = (T + rows_per_block - 1) / rows_per_block;
    ctc_argmax_kernel<<<blocks, threads>>>(emission, out_index, T);

    const int threads2 = 256;
    const int blocks2 = (T + threads2 - 1) / threads2;
    ctc_keep_kernel<<<blocks2, threads2>>>(out_index, out_keep, T);
}

// round 3
// speedup vs baseline: 1.0276x; 1.0276x over previous
#include <cuda_runtime.h>
#include <math_constants.h>

// Fused greedy-CTC kernel.
// Block b (32 warps) computes argmax of rows [31b - 1, 31b + 31):
//   warp w -> row 31b - 1 + w.
// Warps 1..31 write index for their row; the warp-0 row is the boundary row,
// recomputed redundantly (deterministic -> identical to its owner block's value).
// Indices are shared via smem; threads 0..30 then emit keep[31b + i].
#define ROWS_OUT 31

__device__ __forceinline__ int ctc_char(int i) {
    // i < 0 encodes "row -1" sentinel -> prev char -2
    if (i < 0) return -2;
    return (i == 0) ? -1 : ((i > 1) ? (i - 1) : 0);
}

__global__ __launch_bounds__(1024, 1)
void ctc_fused_kernel(const float* __restrict__ em,
                      float* __restrict__ out_index,
                      float* __restrict__ out_keep,
                      int T) {
    __shared__ int s_idx[32];

    const int w    = threadIdx.x >> 5;   // 0..31
    const int lane = threadIdx.x & 31;
    const long long row = (long long)blockIdx.x * ROWS_OUT - 1 + w;

    int bidx = -1;                        // sentinel: row out of range
    if (row >= 0 && row < T) {
        const float4* __restrict__ p =
            reinterpret_cast<const float4*>(em + (size_t)row * 512);

        float best = -CUDART_INF_F;
        int bi = 0x7fffffff;

        #pragma unroll
        for (int j = 0; j < 4; j++) {
            const int v4 = lane + 32 * j;
            const float4 v = __ldg(&p[v4]);
            const int base = v4 * 4;
            if (v.x > best || (v.x == best && base + 0 < bi)) { best = v.x; bi = base + 0; }
            if (v.y > best || (v.y == best && base + 1 < bi)) { best = v.y; bi = base + 1; }
            if (v.z > best || (v.z == best && base + 2 < bi)) { best = v.z; bi = base + 2; }
            if (v.w > best || (v.w == best && base + 3 < bi)) { best = v.w; bi = base + 3; }
        }

        // warp argmax reduction, first-occurrence tie-break
        #pragma unroll
        for (int off = 16; off > 0; off >>= 1) {
            float ov = __shfl_down_sync(0xffffffffu, best, off);
            int   oi = __shfl_down_sync(0xffffffffu, bi, off);
            if (ov > best || (ov == best && oi < bi)) { best = ov; bi = oi; }
        }
        bidx = __shfl_sync(0xffffffffu, bi, 0);

        // warps 1..31 own their row's index output
        if (w >= 1 && lane == 0) out_index[row] = (float)bidx;
    }
    if (lane == 0) s_idx[w] = bidx;
    __syncthreads();

    // keep for rows 31b + i, i = 0..30  (thread i uses s_idx[i] as prev, s_idx[i+1] as cur)
    if (threadIdx.x < ROWS_OUT) {
        const long long t = (long long)blockIdx.x * ROWS_OUT + threadIdx.x;
        if (t < T) {
            const int c  = ctc_char(s_idx[threadIdx.x + 1]);
            const int pc = ctc_char(s_idx[threadIdx.x]);
            out_keep[t] = (c != pc && c != -1) ? 1.0f : 0.0f;
        }
    }
}

extern "C" void kernel_launch(void* const* d_in, const int* in_sizes, int n_in,
                              void* d_out, int out_size) {
    const float* emission = (const float*)d_in[0];
    const int V = 512;
    const int T = in_sizes[0] / V;   // 65536

    float* out = (float*)d_out;      // [0:T] index (as float), [T:2T] keep (0/1)
    float* out_index = out;
    float* out_keep  = out + T;

    const int blocks = (T + ROWS_OUT - 1) / ROWS_OUT;   // 2115
    ctc_fused_kernel<<<blocks, 1024>>>(emission, out_index, out_keep, T);
}